// round 13
// baseline (speedup 1.0000x reference)
#include <cuda_runtime.h>
#include <math.h>

// B=131072, D=512, N=1.
// loss_b = log1p(exp((dot(img,neg) - dot(img,pos)) / 50)); output = mean_b loss_b.
// Persistent single-wave kernel: 888 blocks (148 SM x 6 CTA), 256 threads.
// Each warp walks rows with stride TOTAL_WARPS, #pragma unroll 1 (keeps the
// R6-proven 12-load body per iteration, no front-batching). One acq_rel
// ticket per block; last block reduces 888 partials and writes the mean.

#define B_TOTAL 131072
#define D_F4 128              // 512 floats = 128 float4 per row
#define WARPS_PER_BLOCK 8
#define THREADS 256
#define NBLOCKS 888                               // 148 SMs * 6 CTAs = one wave
#define TOTAL_WARPS (NBLOCKS * WARPS_PER_BLOCK)   // 7104

__device__ __align__(16) float g_partial[NBLOCKS];
__device__ unsigned int g_ticket = 0;   // last block resets to 0 each run

__device__ __forceinline__ unsigned int ticket_acq_rel(unsigned int* p) {
    unsigned int old;
    asm volatile("atom.acq_rel.gpu.global.add.u32 %0, [%1], 1;"
                 : "=r"(old) : "l"(p) : "memory");
    return old;
}

__global__ __launch_bounds__(THREADS, 6) void loss_persistent(
    const float4* __restrict__ img,
    const float4* __restrict__ pos,
    const float4* __restrict__ neg,
    float* __restrict__ out)
{
    const int wid  = threadIdx.x >> 5;
    const int lane = threadIdx.x & 31;
    const unsigned warp_g = blockIdx.x * WARPS_PER_BLOCK + wid;

    float loss = 0.0f;

#pragma unroll 1
    for (unsigned row = warp_g; row < B_TOTAL; row += TOTAL_WARPS) {
        const size_t base = (size_t)row * D_F4 + lane;

        float dp = 0.0f, dn = 0.0f;
#pragma unroll
        for (int i = 0; i < 4; i++) {
            const float4 a = __ldg(img + base + i * 32);
            const float4 p = __ldg(pos + base + i * 32);
            const float4 n = __ldg(neg + base + i * 32);
            dp += a.x * p.x + a.y * p.y + a.z * p.z + a.w * p.w;
            dn += a.x * n.x + a.y * n.y + a.z * n.z + a.w * n.w;
        }

#pragma unroll
        for (int off = 16; off; off >>= 1) {
            dp += __shfl_xor_sync(0xffffffffu, dp, off);
            dn += __shfl_xor_sync(0xffffffffu, dn, off);
        }

        // -log(ep/(ep+en)) == log1p(exp((dn-dp)/50)); redundant on all lanes,
        // only lane0's accumulator is consumed below.
        loss += log1pf(expf((dn - dp) * 0.02f));
    }

    __shared__ float s_loss[WARPS_PER_BLOCK];
    __shared__ bool  s_last;
    if (lane == 0) s_loss[wid] = loss;
    __syncthreads();

    if (threadIdx.x == 0) {
        float sum = 0.0f;
#pragma unroll
        for (int i = 0; i < WARPS_PER_BLOCK; i++) sum += s_loss[i];
        g_partial[blockIdx.x] = sum;                    // plain STG (L2)
        // release orders the STG before the ticket; acquire on the last
        // block makes all prior partials visible.
        s_last = (ticket_acq_rel(&g_ticket) == NBLOCKS - 1);
    }
    __syncthreads();

    if (s_last) {
        float acc = 0.0f;
        for (int i = threadIdx.x; i < NBLOCKS; i += THREADS) {
            acc += __ldcg(&g_partial[i]);               // L2-direct, skip L1
        }
#pragma unroll
        for (int off = 16; off; off >>= 1)
            acc += __shfl_xor_sync(0xffffffffu, acc, off);

        __shared__ float s_fin[WARPS_PER_BLOCK];
        if (lane == 0) s_fin[wid] = acc;
        __syncthreads();
        if (threadIdx.x == 0) {
            float tot = 0.0f;
#pragma unroll
            for (int i = 0; i < WARPS_PER_BLOCK; i++) tot += s_fin[i];
            out[0] = tot / (float)B_TOTAL;
            g_ticket = 0;                   // reset for next graph replay
        }
    }
}

extern "C" void kernel_launch(void* const* d_in, const int* in_sizes, int n_in,
                              void* d_out, int out_size) {
    (void)in_sizes; (void)n_in; (void)out_size;
    const float4* img = (const float4*)d_in[0];
    const float4* pos = (const float4*)d_in[1];
    const float4* neg = (const float4*)d_in[2];
    float* out = (float*)d_out;

    loss_persistent<<<NBLOCKS, THREADS>>>(img, pos, neg, out);
}